// round 3
// baseline (speedup 1.0000x reference)
#include <cuda_runtime.h>
#include <math.h>

#define NN 50000
#define EE 850000

// -------- device scratch (no allocations allowed) --------
__device__ int g_deg[NN];
__device__ int g_cursor[NN];
__device__ int g_rowptr[NN + 1];
__device__ int g_srcs[EE];
__device__ float g_xl[(size_t)NN * 128];
__device__ float g_xr[(size_t)NN * 128];
__device__ float g_h[(size_t)NN * 128];
__device__ float g_wt[4 * 8192];   // transposed weights

// ---------------- f32x2 packed math helpers ----------------
__device__ __forceinline__ unsigned long long pack2(float x) {
    unsigned long long r;
    asm("mov.b64 %0, {%1, %1};" : "=l"(r) : "f"(x));
    return r;
}
__device__ __forceinline__ unsigned long long fma2(unsigned long long a,
                                                   unsigned long long b,
                                                   unsigned long long c) {
    unsigned long long d;
    asm("fma.rn.f32x2 %0, %1, %2, %3;" : "=l"(d) : "l"(a), "l"(b), "l"(c));
    return d;
}
__device__ __forceinline__ float2 unpack2(unsigned long long v) {
    float2 r;
    asm("mov.b64 {%0, %1}, %2;" : "=f"(r.x), "=f"(r.y) : "l"(v));
    return r;
}

// ---------------- CSR build ----------------

__global__ void count_kernel(const int* __restrict__ dst, int e) {
    int i = blockIdx.x * blockDim.x + threadIdx.x;
    if (i < e) atomicAdd(&g_deg[dst[i]], 1);
}

__global__ void scan_kernel(int n) {
    __shared__ int sdata[1024];
    int t = threadIdx.x;
    int ch = (n + 1023) >> 10;
    int s0 = t * ch;
    int s1 = min(s0 + ch, n);
    int sum = 0;
    for (int i = s0; i < s1; i++) sum += g_deg[i];
    sdata[t] = sum;
    __syncthreads();
    for (int off = 1; off < 1024; off <<= 1) {
        int v = (t >= off) ? sdata[t - off] : 0;
        __syncthreads();
        sdata[t] += v;
        __syncthreads();
    }
    int run = sdata[t] - sum;
    for (int i = s0; i < s1; i++) {
        g_rowptr[i] = run;
        g_cursor[i] = run;
        run += g_deg[i];
    }
    if (t == 1023) g_rowptr[n] = run;
}

__global__ void scatter_kernel(const int* __restrict__ src,
                               const int* __restrict__ dst, int e) {
    int i = blockIdx.x * blockDim.x + threadIdx.x;
    if (i < e) {
        int d = dst[i];
        int p = atomicAdd(&g_cursor[d], 1);
        g_srcs[p] = src[i];
    }
}

// ---------------- weight transpose (tiny, once per launch) ----------------
// g_wt layout: [0]=Wl1t(64x128) [1]=Wr1t(64x128) [2]=Wl2t(128x64) [3]=Wr2t(128x64)
__global__ void wt_kernel(const float* __restrict__ Wl1,
                          const float* __restrict__ Wr1,
                          const float* __restrict__ Wl2,
                          const float* __restrict__ Wr2) {
    int idx = blockIdx.x * blockDim.x + threadIdx.x;   // 0 .. 32767
    int m = idx >> 13;
    int r = idx & 8191;
    const float* W = (m == 0) ? Wl1 : (m == 1) ? Wr1 : (m == 2) ? Wl2 : Wr2;
    int fin = (m < 2) ? 64 : 128;
    int fout = (m < 2) ? 128 : 64;
    int k = r / fout;
    int o = r - k * fout;
    g_wt[idx] = W[o * fin + k];   // Wt[k][o] = W[o][k]
}

// ---------------- smem-free dual linear: y = x @ W^T + b ----------------
// blockIdx.y selects (Wt0,b0,y0) vs (Wt1,b1,y1). Wt is [FIN][FOUT] so the
// weight vector load is coalesced LDG.128 (L1-resident after warm-up); x is
// read in natural layout as broadcast LDG.128 (1 wavefront per load).
// Inner loop uses packed fma.rn.f32x2: Wt pairs come packed for free from the
// ulonglong2 load; only the broadcast x scalar needs a mov.b64 pack.
template <int FIN, int FOUT>
__global__ void __launch_bounds__(256)
linear2_kernel(const float* __restrict__ x,
               const float* __restrict__ Wt0,
               const float* __restrict__ b0,
               float* __restrict__ y0,
               const float* __restrict__ Wt1,
               const float* __restrict__ b1,
               float* __restrict__ y1,
               int n) {
    constexpr int BN = 64;
    constexpr int OT = FOUT / 4;     // 32 or 16
    constexpr int NT = 256 / OT;     // 8 or 16
    constexpr int NPT = BN / NT;     // 8 or 4

    const float* Wt = blockIdx.y ? Wt1 : Wt0;
    const float* b = blockIdx.y ? b1 : b0;
    float* y = blockIdx.y ? y1 : y0;

    int tid = threadIdx.x;
    int ot = tid % OT;
    int nt = tid / OT;
    int n0 = blockIdx.x * BN + nt * NPT;

    int nodes[NPT];
#pragma unroll
    for (int i = 0; i < NPT; i++) nodes[i] = min(n0 + i, n - 1);

    unsigned long long acc[NPT][2];
#pragma unroll
    for (int i = 0; i < NPT; i++) { acc[i][0] = 0ull; acc[i][1] = 0ull; }

    const float* wbase = Wt + 4 * ot;

#pragma unroll 2
    for (int k = 0; k < FIN; k += 4) {
        unsigned long long wv[4][2];
#pragma unroll
        for (int r = 0; r < 4; r++) {
            ulonglong2 t = *(const ulonglong2*)(wbase + (k + r) * FOUT);
            wv[r][0] = t.x;
            wv[r][1] = t.y;
        }
#pragma unroll
        for (int i = 0; i < NPT; i++) {
            float4 xv = __ldg((const float4*)(x + (size_t)nodes[i] * FIN + k));
            unsigned long long x0 = pack2(xv.x);
            unsigned long long x1 = pack2(xv.y);
            unsigned long long x2 = pack2(xv.z);
            unsigned long long x3 = pack2(xv.w);
            acc[i][0] = fma2(x0, wv[0][0], acc[i][0]);
            acc[i][1] = fma2(x0, wv[0][1], acc[i][1]);
            acc[i][0] = fma2(x1, wv[1][0], acc[i][0]);
            acc[i][1] = fma2(x1, wv[1][1], acc[i][1]);
            acc[i][0] = fma2(x2, wv[2][0], acc[i][0]);
            acc[i][1] = fma2(x2, wv[2][1], acc[i][1]);
            acc[i][0] = fma2(x3, wv[3][0], acc[i][0]);
            acc[i][1] = fma2(x3, wv[3][1], acc[i][1]);
        }
    }

    float4 bv = *(const float4*)(b + 4 * ot);
#pragma unroll
    for (int i = 0; i < NPT; i++) {
        int node = n0 + i;
        if (node < n) {
            float2 lo = unpack2(acc[i][0]);
            float2 hi = unpack2(acc[i][1]);
            float4 o4 = make_float4(lo.x + bv.x, lo.y + bv.y,
                                    hi.x + bv.z, hi.y + bv.w);
            *(float4*)(y + (size_t)node * FOUT + 4 * ot) = o4;
        }
    }
}

// ---------------- fused GATv2 edge phase ----------------
template <int H, int C, bool ELU>
__global__ void gat_kernel(const float* __restrict__ xl,
                           const float* __restrict__ xr,
                           const float* __restrict__ att,
                           const float* __restrict__ bias,
                           float* __restrict__ out, int n) {
    constexpr int F = H * C;
    constexpr int V = F / 32;
    constexpr int G = 32 / H;

    int wid = (blockIdx.x * blockDim.x + threadIdx.x) >> 5;
    int lane = threadIdx.x & 31;
    if (wid >= n) return;
    int i = wid;
    int cbase = lane * V;

    float xrv[V], attv[V], acc[V];
    {
        const float* xp = xr + (size_t)i * F + cbase;
        if constexpr (V == 4) {
            float4 t = *(const float4*)xp;
            xrv[0] = t.x; xrv[1] = t.y; xrv[2] = t.z; xrv[3] = t.w;
        } else {
            float2 t = *(const float2*)xp;
            xrv[0] = t.x; xrv[1] = t.y;
        }
    }
#pragma unroll
    for (int j = 0; j < V; j++) { attv[j] = att[cbase + j]; acc[j] = 0.f; }

    float m = -1e30f, z = 0.f;
    int beg = g_rowptr[i], end = g_rowptr[i + 1];

    auto process = [&](const float* __restrict__ xlv) {
        float part = 0.f;
#pragma unroll
        for (int j = 0; j < V; j++) {
            float s = xlv[j] + xrv[j];
            s = (s > 0.f) ? s : 0.2f * s;
            part += s * attv[j];
        }
#pragma unroll
        for (int off = G / 2; off > 0; off >>= 1)
            part += __shfl_xor_sync(0xffffffffu, part, off);
        float e = part;
        float nm = fmaxf(m, e);
        float sc = __expf(m - nm);
        float p = __expf(e - nm);
        z = z * sc + p;
#pragma unroll
        for (int j = 0; j < V; j++) acc[j] = acc[j] * sc + p * xlv[j];
        m = nm;
    };

    int k = beg;
    for (; k + 1 < end; k += 2) {
        int s0 = g_srcs[k];
        int s1 = g_srcs[k + 1];
        float a0[V], a1[V];
        const float* p0 = xl + (size_t)s0 * F + cbase;
        const float* p1 = xl + (size_t)s1 * F + cbase;
        if constexpr (V == 4) {
            float4 t0 = *(const float4*)p0;
            float4 t1 = *(const float4*)p1;
            a0[0] = t0.x; a0[1] = t0.y; a0[2] = t0.z; a0[3] = t0.w;
            a1[0] = t1.x; a1[1] = t1.y; a1[2] = t1.z; a1[3] = t1.w;
        } else {
            float2 t0 = *(const float2*)p0;
            float2 t1 = *(const float2*)p1;
            a0[0] = t0.x; a0[1] = t0.y;
            a1[0] = t1.x; a1[1] = t1.y;
        }
        process(a0);
        process(a1);
    }
    if (k < end) {
        int s0 = g_srcs[k];
        float a0[V];
        const float* p0 = xl + (size_t)s0 * F + cbase;
        if constexpr (V == 4) {
            float4 t0 = *(const float4*)p0;
            a0[0] = t0.x; a0[1] = t0.y; a0[2] = t0.z; a0[3] = t0.w;
        } else {
            float2 t0 = *(const float2*)p0;
            a0[0] = t0.x; a0[1] = t0.y;
        }
        process(a0);
    }

    float inv = 1.f / (z + 1e-16f);
    float ov[V];
#pragma unroll
    for (int j = 0; j < V; j++) {
        float v = acc[j] * inv + bias[cbase + j];
        if constexpr (ELU) v = (v > 0.f) ? v : (__expf(v) - 1.f);
        ov[j] = v;
    }
    float* op = out + (size_t)i * F + cbase;
    if constexpr (V == 4)
        *(float4*)op = make_float4(ov[0], ov[1], ov[2], ov[3]);
    else
        *(float2*)op = make_float2(ov[0], ov[1]);
}

// ---------------- launch ----------------

extern "C" void kernel_launch(void* const* d_in, const int* in_sizes, int n_in,
                              void* d_out, int out_size) {
    const float* x    = (const float*)d_in[0];
    const int*   ei   = (const int*)d_in[1];
    const float* Wl1  = (const float*)d_in[2];
    const float* bl1  = (const float*)d_in[3];
    const float* Wr1  = (const float*)d_in[4];
    const float* br1  = (const float*)d_in[5];
    const float* att1 = (const float*)d_in[6];
    const float* bias1= (const float*)d_in[7];
    const float* Wl2  = (const float*)d_in[8];
    const float* bl2  = (const float*)d_in[9];
    const float* Wr2  = (const float*)d_in[10];
    const float* br2  = (const float*)d_in[11];
    const float* att2 = (const float*)d_in[12];
    const float* bias2= (const float*)d_in[13];
    float* out = (float*)d_out;

    int n = in_sizes[0] / 64;   // 50000
    int e = in_sizes[1] / 2;    // 850000
    const int* src = ei;
    const int* dst = ei + e;

    float *xlp, *xrp, *hp, *wtp;
    int* degp;
    cudaGetSymbolAddress((void**)&xlp, g_xl);
    cudaGetSymbolAddress((void**)&xrp, g_xr);
    cudaGetSymbolAddress((void**)&hp,  g_h);
    cudaGetSymbolAddress((void**)&wtp, g_wt);
    cudaGetSymbolAddress((void**)&degp, g_deg);

    // CSR by dst
    cudaMemsetAsync(degp, 0, n * sizeof(int));
    count_kernel<<<(e + 255) / 256, 256>>>(dst, e);
    scan_kernel<<<1, 1024>>>(n);
    scatter_kernel<<<(e + 255) / 256, 256>>>(src, dst, e);

    // transpose weights (tiny)
    wt_kernel<<<128, 256>>>(Wl1, Wr1, Wl2, Wr2);

    dim3 lgrid((n + 63) / 64, 2);

    // layer 1: 64 -> 4x32 (concat) -> ELU
    linear2_kernel<64, 128><<<lgrid, 256>>>(
        x, wtp, bl1, xlp, wtp + 8192, br1, xrp, n);
    gat_kernel<4, 32, true><<<(n + 7) / 8, 256>>>(xlp, xrp, att1, bias1, hp, n);

    // layer 2: 128 -> 1x64 (mean over 1 head == identity)
    linear2_kernel<128, 64><<<lgrid, 256>>>(
        hp, wtp + 16384, bl2, xlp, wtp + 24576, br2, xrp, n);
    gat_kernel<1, 64, false><<<(n + 7) / 8, 256>>>(xlp, xrp, att2, bias2, out, n);
}

// round 4
// speedup vs baseline: 1.1887x; 1.1887x over previous
#include <cuda_runtime.h>
#include <math.h>

#define NN 50000
#define EE 850000

// -------- device scratch (no allocations allowed) --------
__device__ int g_deg[NN];
__device__ int g_cursor[NN];
__device__ int g_rowptr[NN + 1];
__device__ int g_srcs[EE];
__device__ float g_xl[(size_t)NN * 128];
__device__ float g_xr[(size_t)NN * 128];
__device__ float g_h[(size_t)NN * 128];
__device__ float g_wt[4 * 8192];   // transposed weights

// ---------------- f32x2 packed math helpers ----------------
__device__ __forceinline__ unsigned long long pack2(float x) {
    unsigned long long r;
    asm("mov.b64 %0, {%1, %1};" : "=l"(r) : "f"(x));
    return r;
}
__device__ __forceinline__ unsigned long long fma2(unsigned long long a,
                                                   unsigned long long b,
                                                   unsigned long long c) {
    unsigned long long d;
    asm("fma.rn.f32x2 %0, %1, %2, %3;" : "=l"(d) : "l"(a), "l"(b), "l"(c));
    return d;
}
__device__ __forceinline__ float2 unpack2(unsigned long long v) {
    float2 r;
    asm("mov.b64 {%0, %1}, %2;" : "=f"(r.x), "=f"(r.y) : "l"(v));
    return r;
}

// ---------------- CSR build ----------------

__global__ void count_kernel(const int* __restrict__ dst, int e) {
    int i = blockIdx.x * blockDim.x + threadIdx.x;
    if (i < e) atomicAdd(&g_deg[dst[i]], 1);
}

__global__ void scan_kernel(int n) {
    __shared__ int sdata[1024];
    int t = threadIdx.x;
    int ch = (n + 1023) >> 10;
    int s0 = t * ch;
    int s1 = min(s0 + ch, n);
    int sum = 0;
    for (int i = s0; i < s1; i++) sum += g_deg[i];
    sdata[t] = sum;
    __syncthreads();
    for (int off = 1; off < 1024; off <<= 1) {
        int v = (t >= off) ? sdata[t - off] : 0;
        __syncthreads();
        sdata[t] += v;
        __syncthreads();
    }
    int run = sdata[t] - sum;
    for (int i = s0; i < s1; i++) {
        g_rowptr[i] = run;
        g_cursor[i] = run;
        run += g_deg[i];
    }
    if (t == 1023) g_rowptr[n] = run;
}

__global__ void scatter_kernel(const int* __restrict__ src,
                               const int* __restrict__ dst, int e) {
    int i = blockIdx.x * blockDim.x + threadIdx.x;
    if (i < e) {
        int d = dst[i];
        int p = atomicAdd(&g_cursor[d], 1);
        g_srcs[p] = src[i];
    }
}

// ---------------- weight transpose (tiny, once per launch) ----------------
__global__ void wt_kernel(const float* __restrict__ Wl1,
                          const float* __restrict__ Wr1,
                          const float* __restrict__ Wl2,
                          const float* __restrict__ Wr2) {
    int idx = blockIdx.x * blockDim.x + threadIdx.x;   // 0 .. 32767
    int m = idx >> 13;
    int r = idx & 8191;
    const float* W = (m == 0) ? Wl1 : (m == 1) ? Wr1 : (m == 2) ? Wl2 : Wr2;
    int fin = (m < 2) ? 64 : 128;
    int fout = (m < 2) ? 128 : 64;
    int k = r / fout;
    int o = r - k * fout;
    g_wt[idx] = W[o * fin + k];   // Wt[k][o] = W[o][k]
}

// ---------------- smem dual linear: y = x @ W^T + b ----------------
// Conflict-free staging (Wt rows copied straight; sX transposed with
// consecutive-thread -> consecutive-bank writes). Inner loop: node-paired
// fma.rn.f32x2 — x pairs packed for free, weights broadcast-packed.
template <int FIN, int FOUT>
__global__ void __launch_bounds__(256)
linear2_kernel(const float* __restrict__ x,
               const float* __restrict__ Wt0,
               const float* __restrict__ b0,
               float* __restrict__ y0,
               const float* __restrict__ Wt1,
               const float* __restrict__ b1,
               float* __restrict__ y1,
               int n) {
    constexpr int BN = 64;
    constexpr int KC = 32;
    constexpr int OT = FOUT / 4;     // 32 or 16
    constexpr int NT = 256 / OT;     // 8 or 16
    constexpr int NPT = BN / NT;     // 8 or 4
    constexpr int NP = NPT / 2;      // node pairs per thread: 4 or 2

    __shared__ float sW[KC * FOUT];
    __shared__ float sX[KC * BN];

    const float* Wt = blockIdx.y ? Wt1 : Wt0;
    const float* b = blockIdx.y ? b1 : b0;
    float* y = blockIdx.y ? y1 : y0;

    int tid = threadIdx.x;
    int ot = tid % OT;
    int nt = tid / OT;
    int nbase = blockIdx.x * BN;
    int n0 = nt * NPT;

    unsigned long long acc[NP][4];
#pragma unroll
    for (int q = 0; q < NP; q++)
#pragma unroll
        for (int j = 0; j < 4; j++) acc[q][j] = 0ull;

    for (int kc = 0; kc < FIN; kc += KC) {
        __syncthreads();
        // stage W chunk: straight coalesced copy (Wt already [FIN][FOUT])
        {
            const float4* wsrc = (const float4*)(Wt + (size_t)kc * FOUT);
#pragma unroll
            for (int idx = tid; idx < KC * FOUT / 4; idx += 256)
                ((float4*)sW)[idx] = wsrc[idx];
        }
        // stage X transposed: sX[k][nn]; consecutive tid -> consecutive nn
#pragma unroll
        for (int idx = tid; idx < (KC / 4) * BN; idx += 256) {
            int nn = idx % BN;
            int c4 = idx / BN;
            int node = nbase + nn;
            float4 xv = make_float4(0.f, 0.f, 0.f, 0.f);
            if (node < n) xv = *(const float4*)(x + (size_t)node * FIN + kc + 4 * c4);
            sX[(4 * c4 + 0) * BN + nn] = xv.x;
            sX[(4 * c4 + 1) * BN + nn] = xv.y;
            sX[(4 * c4 + 2) * BN + nn] = xv.z;
            sX[(4 * c4 + 3) * BN + nn] = xv.w;
        }
        __syncthreads();

#pragma unroll 8
        for (int k = 0; k < KC; k++) {
            float4 w = *(const float4*)(sW + k * FOUT + 4 * ot);
            unsigned long long w0 = pack2(w.x);
            unsigned long long w1 = pack2(w.y);
            unsigned long long w2 = pack2(w.z);
            unsigned long long w3 = pack2(w.w);
            const ulonglong2* xp = (const ulonglong2*)(sX + k * BN + n0);
#pragma unroll
            for (int q2 = 0; q2 < NP / 2; q2++) {
                ulonglong2 xv = xp[q2];
                acc[2 * q2][0] = fma2(xv.x, w0, acc[2 * q2][0]);
                acc[2 * q2][1] = fma2(xv.x, w1, acc[2 * q2][1]);
                acc[2 * q2][2] = fma2(xv.x, w2, acc[2 * q2][2]);
                acc[2 * q2][3] = fma2(xv.x, w3, acc[2 * q2][3]);
                acc[2 * q2 + 1][0] = fma2(xv.y, w0, acc[2 * q2 + 1][0]);
                acc[2 * q2 + 1][1] = fma2(xv.y, w1, acc[2 * q2 + 1][1]);
                acc[2 * q2 + 1][2] = fma2(xv.y, w2, acc[2 * q2 + 1][2]);
                acc[2 * q2 + 1][3] = fma2(xv.y, w3, acc[2 * q2 + 1][3]);
            }
        }
    }

    float4 bv = *(const float4*)(b + 4 * ot);
#pragma unroll
    for (int q = 0; q < NP; q++) {
        float2 o0 = unpack2(acc[q][0]);
        float2 o1 = unpack2(acc[q][1]);
        float2 o2 = unpack2(acc[q][2]);
        float2 o3 = unpack2(acc[q][3]);
        int na = nbase + n0 + 2 * q;
        if (na < n)
            *(float4*)(y + (size_t)na * FOUT + 4 * ot) =
                make_float4(o0.x + bv.x, o1.x + bv.y, o2.x + bv.z, o3.x + bv.w);
        if (na + 1 < n)
            *(float4*)(y + (size_t)(na + 1) * FOUT + 4 * ot) =
                make_float4(o0.y + bv.x, o1.y + bv.y, o2.y + bv.z, o3.y + bv.w);
    }
}

// ---------------- fused GATv2 edge phase ----------------
// One warp per destination node. Direct exp (no max subtraction — exact
// softmax identity; |e| << 88 here so no overflow), 4-edge software pipeline.
template <int H, int C, bool ELU>
__global__ void gat_kernel(const float* __restrict__ xl,
                           const float* __restrict__ xr,
                           const float* __restrict__ att,
                           const float* __restrict__ bias,
                           float* __restrict__ out, int n) {
    constexpr int F = H * C;
    constexpr int V = F / 32;
    constexpr int G = 32 / H;

    int wid = (blockIdx.x * blockDim.x + threadIdx.x) >> 5;
    int lane = threadIdx.x & 31;
    if (wid >= n) return;
    int i = wid;
    int cbase = lane * V;

    float xrv[V], attv[V], acc[V];
    {
        const float* xp = xr + (size_t)i * F + cbase;
        if constexpr (V == 4) {
            float4 t = *(const float4*)xp;
            xrv[0] = t.x; xrv[1] = t.y; xrv[2] = t.z; xrv[3] = t.w;
        } else {
            float2 t = *(const float2*)xp;
            xrv[0] = t.x; xrv[1] = t.y;
        }
    }
#pragma unroll
    for (int j = 0; j < V; j++) { attv[j] = att[cbase + j]; acc[j] = 0.f; }

    float z = 0.f;
    int beg = g_rowptr[i], end = g_rowptr[i + 1];
    int k = beg;

    for (; k + 4 <= end; k += 4) {
        int s0 = __ldg(g_srcs + k);
        int s1 = __ldg(g_srcs + k + 1);
        int s2 = __ldg(g_srcs + k + 2);
        int s3 = __ldg(g_srcs + k + 3);
        float a[4][V];
        const float* p0 = xl + (size_t)s0 * F + cbase;
        const float* p1 = xl + (size_t)s1 * F + cbase;
        const float* p2 = xl + (size_t)s2 * F + cbase;
        const float* p3 = xl + (size_t)s3 * F + cbase;
        if constexpr (V == 4) {
            float4 t0 = *(const float4*)p0;
            float4 t1 = *(const float4*)p1;
            float4 t2 = *(const float4*)p2;
            float4 t3 = *(const float4*)p3;
            a[0][0]=t0.x; a[0][1]=t0.y; a[0][2]=t0.z; a[0][3]=t0.w;
            a[1][0]=t1.x; a[1][1]=t1.y; a[1][2]=t1.z; a[1][3]=t1.w;
            a[2][0]=t2.x; a[2][1]=t2.y; a[2][2]=t2.z; a[2][3]=t2.w;
            a[3][0]=t3.x; a[3][1]=t3.y; a[3][2]=t3.z; a[3][3]=t3.w;
        } else {
            float2 t0 = *(const float2*)p0;
            float2 t1 = *(const float2*)p1;
            float2 t2 = *(const float2*)p2;
            float2 t3 = *(const float2*)p3;
            a[0][0]=t0.x; a[0][1]=t0.y;
            a[1][0]=t1.x; a[1][1]=t1.y;
            a[2][0]=t2.x; a[2][1]=t2.y;
            a[3][0]=t3.x; a[3][1]=t3.y;
        }
        float part[4];
#pragma unroll
        for (int e4 = 0; e4 < 4; e4++) {
            float pp = 0.f;
#pragma unroll
            for (int j = 0; j < V; j++) {
                float s = a[e4][j] + xrv[j];
                s = (s > 0.f) ? s : 0.2f * s;
                pp += s * attv[j];
            }
            part[e4] = pp;
        }
        // interleaved shfl stages: 4 independent shfls per stage
#pragma unroll
        for (int off = G / 2; off > 0; off >>= 1) {
#pragma unroll
            for (int e4 = 0; e4 < 4; e4++)
                part[e4] += __shfl_xor_sync(0xffffffffu, part[e4], off);
        }
        float p0v = __expf(part[0]);
        float p1v = __expf(part[1]);
        float p2v = __expf(part[2]);
        float p3v = __expf(part[3]);
        z += (p0v + p1v) + (p2v + p3v);
#pragma unroll
        for (int j = 0; j < V; j++)
            acc[j] += p0v * a[0][j] + p1v * a[1][j] + p2v * a[2][j] + p3v * a[3][j];
    }
    for (; k < end; k++) {
        int s0 = __ldg(g_srcs + k);
        float a0[V];
        const float* p0 = xl + (size_t)s0 * F + cbase;
        if constexpr (V == 4) {
            float4 t0 = *(const float4*)p0;
            a0[0] = t0.x; a0[1] = t0.y; a0[2] = t0.z; a0[3] = t0.w;
        } else {
            float2 t0 = *(const float2*)p0;
            a0[0] = t0.x; a0[1] = t0.y;
        }
        float pp = 0.f;
#pragma unroll
        for (int j = 0; j < V; j++) {
            float s = a0[j] + xrv[j];
            s = (s > 0.f) ? s : 0.2f * s;
            pp += s * attv[j];
        }
#pragma unroll
        for (int off = G / 2; off > 0; off >>= 1)
            pp += __shfl_xor_sync(0xffffffffu, pp, off);
        float pv = __expf(pp);
        z += pv;
#pragma unroll
        for (int j = 0; j < V; j++) acc[j] += pv * a0[j];
    }

    float inv = 1.f / (z + 1e-16f);
    float ov[V];
#pragma unroll
    for (int j = 0; j < V; j++) {
        float v = acc[j] * inv + bias[cbase + j];
        if constexpr (ELU) v = (v > 0.f) ? v : (__expf(v) - 1.f);
        ov[j] = v;
    }
    float* op = out + (size_t)i * F + cbase;
    if constexpr (V == 4)
        *(float4*)op = make_float4(ov[0], ov[1], ov[2], ov[3]);
    else
        *(float2*)op = make_float2(ov[0], ov[1]);
}

// ---------------- launch ----------------

extern "C" void kernel_launch(void* const* d_in, const int* in_sizes, int n_in,
                              void* d_out, int out_size) {
    const float* x    = (const float*)d_in[0];
    const int*   ei   = (const int*)d_in[1];
    const float* Wl1  = (const float*)d_in[2];
    const float* bl1  = (const float*)d_in[3];
    const float* Wr1  = (const float*)d_in[4];
    const float* br1  = (const float*)d_in[5];
    const float* att1 = (const float*)d_in[6];
    const float* bias1= (const float*)d_in[7];
    const float* Wl2  = (const float*)d_in[8];
    const float* bl2  = (const float*)d_in[9];
    const float* Wr2  = (const float*)d_in[10];
    const float* br2  = (const float*)d_in[11];
    const float* att2 = (const float*)d_in[12];
    const float* bias2= (const float*)d_in[13];
    float* out = (float*)d_out;

    int n = in_sizes[0] / 64;   // 50000
    int e = in_sizes[1] / 2;    // 850000
    const int* src = ei;
    const int* dst = ei + e;

    float *xlp, *xrp, *hp, *wtp;
    int* degp;
    cudaGetSymbolAddress((void**)&xlp, g_xl);
    cudaGetSymbolAddress((void**)&xrp, g_xr);
    cudaGetSymbolAddress((void**)&hp,  g_h);
    cudaGetSymbolAddress((void**)&wtp, g_wt);
    cudaGetSymbolAddress((void**)&degp, g_deg);

    // CSR by dst
    cudaMemsetAsync(degp, 0, n * sizeof(int));
    count_kernel<<<(e + 255) / 256, 256>>>(dst, e);
    scan_kernel<<<1, 1024>>>(n);
    scatter_kernel<<<(e + 255) / 256, 256>>>(src, dst, e);

    // transpose weights (tiny)
    wt_kernel<<<128, 256>>>(Wl1, Wr1, Wl2, Wr2);

    dim3 lgrid((n + 63) / 64, 2);

    // layer 1: 64 -> 4x32 (concat) -> ELU
    linear2_kernel<64, 128><<<lgrid, 256>>>(
        x, wtp, bl1, xlp, wtp + 8192, br1, xrp, n);
    gat_kernel<4, 32, true><<<(n + 7) / 8, 256>>>(xlp, xrp, att1, bias1, hp, n);

    // layer 2: 128 -> 1x64 (mean over 1 head == identity)
    linear2_kernel<128, 64><<<lgrid, 256>>>(
        hp, wtp + 16384, bl2, xlp, wtp + 24576, br2, xrp, n);
    gat_kernel<1, 64, false><<<(n + 7) / 8, 256>>>(xlp, xrp, att2, bias2, out, n);
}

// round 6
// speedup vs baseline: 1.3826x; 1.1632x over previous
#include <cuda_runtime.h>
#include <math.h>
#include <stdint.h>

#define NN 50000
#define EE 850000

// -------- device scratch (no allocations allowed) --------
__device__ int g_deg[NN];
__device__ int g_cursor[NN];
__device__ int g_rowptr[NN + 1];
__device__ int g_srcs[EE];
__device__ float g_xl[(size_t)NN * 128];
__device__ float g_xr[(size_t)NN * 128];
__device__ float g_h[(size_t)NN * 128];
__device__ float g_wt[4 * 8192];   // transposed weights

// ---------------- f32x2 packed math helpers ----------------
__device__ __forceinline__ unsigned long long pack2(float x) {
    unsigned long long r;
    asm("mov.b64 %0, {%1, %1};" : "=l"(r) : "f"(x));
    return r;
}
__device__ __forceinline__ unsigned long long fma2(unsigned long long a,
                                                   unsigned long long b,
                                                   unsigned long long c) {
    unsigned long long d;
    asm("fma.rn.f32x2 %0, %1, %2, %3;" : "=l"(d) : "l"(a), "l"(b), "l"(c));
    return d;
}
__device__ __forceinline__ float2 unpack2(unsigned long long v) {
    float2 r;
    asm("mov.b64 {%0, %1}, %2;" : "=f"(r.x), "=f"(r.y) : "l"(v));
    return r;
}

// ---------------- CSR build ----------------

// vectorized: 4 edges per thread via int4
__global__ void count_kernel(const int4* __restrict__ dst4, int e4,
                             const int* __restrict__ dst, int e) {
    int i = blockIdx.x * blockDim.x + threadIdx.x;
    if (i < e4) {
        int4 d = dst4[i];
        atomicAdd(&g_deg[d.x], 1);
        atomicAdd(&g_deg[d.y], 1);
        atomicAdd(&g_deg[d.z], 1);
        atomicAdd(&g_deg[d.w], 1);
    }
    if (i == 0) {
        for (int k = 4 * e4; k < e; k++) atomicAdd(&g_deg[dst[k]], 1);
    }
}

__global__ void scan_kernel(int n) {
    __shared__ int sdata[1024];
    int t = threadIdx.x;
    int ch = (n + 1023) >> 10;
    int s0 = t * ch;
    int s1 = min(s0 + ch, n);
    int sum = 0;
    for (int i = s0; i < s1; i++) sum += g_deg[i];
    sdata[t] = sum;
    __syncthreads();
    for (int off = 1; off < 1024; off <<= 1) {
        int v = (t >= off) ? sdata[t - off] : 0;
        __syncthreads();
        sdata[t] += v;
        __syncthreads();
    }
    int run = sdata[t] - sum;
    for (int i = s0; i < s1; i++) {
        g_rowptr[i] = run;
        g_cursor[i] = run;
        run += g_deg[i];
    }
    if (t == 1023) g_rowptr[n] = run;
}

__global__ void scatter_kernel(const int4* __restrict__ src4,
                               const int4* __restrict__ dst4, int e4,
                               const int* __restrict__ src,
                               const int* __restrict__ dst, int e) {
    int i = blockIdx.x * blockDim.x + threadIdx.x;
    if (i < e4) {
        int4 s = src4[i];
        int4 d = dst4[i];
        g_srcs[atomicAdd(&g_cursor[d.x], 1)] = s.x;
        g_srcs[atomicAdd(&g_cursor[d.y], 1)] = s.y;
        g_srcs[atomicAdd(&g_cursor[d.z], 1)] = s.z;
        g_srcs[atomicAdd(&g_cursor[d.w], 1)] = s.w;
    }
    if (i == 0) {
        for (int k = 4 * e4; k < e; k++)
            g_srcs[atomicAdd(&g_cursor[dst[k]], 1)] = src[k];
    }
}

// ---------------- weight transpose (tiny, once per launch) ----------------
__global__ void wt_kernel(const float* __restrict__ Wl1,
                          const float* __restrict__ Wr1,
                          const float* __restrict__ Wl2,
                          const float* __restrict__ Wr2) {
    int idx = blockIdx.x * blockDim.x + threadIdx.x;   // 0 .. 32767
    int m = idx >> 13;
    int r = idx & 8191;
    const float* W = (m == 0) ? Wl1 : (m == 1) ? Wr1 : (m == 2) ? Wl2 : Wr2;
    int fin = (m < 2) ? 64 : 128;
    int fout = (m < 2) ? 128 : 64;
    int k = r / fout;
    int o = r - k * fout;
    g_wt[idx] = W[o * fin + k];   // Wt[k][o] = W[o][k]
}

// ---------------- smem dual linear: y = x @ W^T + b ----------------
template <int FIN, int FOUT>
__global__ void __launch_bounds__(256)
linear2_kernel(const float* __restrict__ x,
               const float* __restrict__ Wt0,
               const float* __restrict__ b0,
               float* __restrict__ y0,
               const float* __restrict__ Wt1,
               const float* __restrict__ b1,
               float* __restrict__ y1,
               int n) {
    constexpr int BN = 64;
    constexpr int KC = 32;
    constexpr int OT = FOUT / 4;     // 32 or 16
    constexpr int NT = 256 / OT;     // 8 or 16
    constexpr int NPT = BN / NT;     // 8 or 4
    constexpr int NP = NPT / 2;      // node pairs per thread: 4 or 2

    __shared__ float sW[KC * FOUT];
    __shared__ float sX[KC * BN];

    const float* Wt = blockIdx.y ? Wt1 : Wt0;
    const float* b = blockIdx.y ? b1 : b0;
    float* y = blockIdx.y ? y1 : y0;

    int tid = threadIdx.x;
    int ot = tid % OT;
    int nt = tid / OT;
    int nbase = blockIdx.x * BN;
    int n0 = nt * NPT;

    unsigned long long acc[NP][4];
#pragma unroll
    for (int q = 0; q < NP; q++)
#pragma unroll
        for (int j = 0; j < 4; j++) acc[q][j] = 0ull;

    for (int kc = 0; kc < FIN; kc += KC) {
        __syncthreads();
        {
            const float4* wsrc = (const float4*)(Wt + (size_t)kc * FOUT);
#pragma unroll
            for (int idx = tid; idx < KC * FOUT / 4; idx += 256)
                ((float4*)sW)[idx] = wsrc[idx];
        }
#pragma unroll
        for (int idx = tid; idx < (KC / 4) * BN; idx += 256) {
            int nn = idx % BN;
            int c4 = idx / BN;
            int node = nbase + nn;
            float4 xv = make_float4(0.f, 0.f, 0.f, 0.f);
            if (node < n) xv = *(const float4*)(x + (size_t)node * FIN + kc + 4 * c4);
            sX[(4 * c4 + 0) * BN + nn] = xv.x;
            sX[(4 * c4 + 1) * BN + nn] = xv.y;
            sX[(4 * c4 + 2) * BN + nn] = xv.z;
            sX[(4 * c4 + 3) * BN + nn] = xv.w;
        }
        __syncthreads();

#pragma unroll 8
        for (int k = 0; k < KC; k++) {
            float4 w = *(const float4*)(sW + k * FOUT + 4 * ot);
            unsigned long long w0 = pack2(w.x);
            unsigned long long w1 = pack2(w.y);
            unsigned long long w2 = pack2(w.z);
            unsigned long long w3 = pack2(w.w);
            const ulonglong2* xp = (const ulonglong2*)(sX + k * BN + n0);
#pragma unroll
            for (int q2 = 0; q2 < NP / 2; q2++) {
                ulonglong2 xv = xp[q2];
                acc[2 * q2][0] = fma2(xv.x, w0, acc[2 * q2][0]);
                acc[2 * q2][1] = fma2(xv.x, w1, acc[2 * q2][1]);
                acc[2 * q2][2] = fma2(xv.x, w2, acc[2 * q2][2]);
                acc[2 * q2][3] = fma2(xv.x, w3, acc[2 * q2][3]);
                acc[2 * q2 + 1][0] = fma2(xv.y, w0, acc[2 * q2 + 1][0]);
                acc[2 * q2 + 1][1] = fma2(xv.y, w1, acc[2 * q2 + 1][1]);
                acc[2 * q2 + 1][2] = fma2(xv.y, w2, acc[2 * q2 + 1][2]);
                acc[2 * q2 + 1][3] = fma2(xv.y, w3, acc[2 * q2 + 1][3]);
            }
        }
    }

    float4 bv = *(const float4*)(b + 4 * ot);
#pragma unroll
    for (int q = 0; q < NP; q++) {
        float2 o0 = unpack2(acc[q][0]);
        float2 o1 = unpack2(acc[q][1]);
        float2 o2 = unpack2(acc[q][2]);
        float2 o3 = unpack2(acc[q][3]);
        int na = nbase + n0 + 2 * q;
        if (na < n)
            *(float4*)(y + (size_t)na * FOUT + 4 * ot) =
                make_float4(o0.x + bv.x, o1.x + bv.y, o2.x + bv.z, o3.x + bv.w);
        if (na + 1 < n)
            *(float4*)(y + (size_t)(na + 1) * FOUT + 4 * ot) =
                make_float4(o0.y + bv.x, o1.y + bv.y, o2.y + bv.z, o3.y + bv.w);
    }
}

// ---------------- fused GATv2 edge phase ----------------
template <int H, int C, bool ELU>
__global__ void gat_kernel(const float* __restrict__ xl,
                           const float* __restrict__ xr,
                           const float* __restrict__ att,
                           const float* __restrict__ bias,
                           float* __restrict__ out, int n) {
    constexpr int F = H * C;
    constexpr int V = F / 32;
    constexpr int G = 32 / H;

    int wid = (blockIdx.x * blockDim.x + threadIdx.x) >> 5;
    int lane = threadIdx.x & 31;
    if (wid >= n) return;
    int i = wid;
    int cbase = lane * V;

    float xrv[V], attv[V], acc[V];
    {
        const float* xp = xr + (size_t)i * F + cbase;
        if constexpr (V == 4) {
            float4 t = *(const float4*)xp;
            xrv[0] = t.x; xrv[1] = t.y; xrv[2] = t.z; xrv[3] = t.w;
        } else {
            float2 t = *(const float2*)xp;
            xrv[0] = t.x; xrv[1] = t.y;
        }
    }
#pragma unroll
    for (int j = 0; j < V; j++) { attv[j] = att[cbase + j]; acc[j] = 0.f; }

    float z = 0.f;
    int beg = g_rowptr[i], end = g_rowptr[i + 1];
    int k = beg;

    for (; k + 4 <= end; k += 4) {
        int s0 = __ldg(g_srcs + k);
        int s1 = __ldg(g_srcs + k + 1);
        int s2 = __ldg(g_srcs + k + 2);
        int s3 = __ldg(g_srcs + k + 3);
        float a[4][V];
        const float* p0 = xl + (size_t)s0 * F + cbase;
        const float* p1 = xl + (size_t)s1 * F + cbase;
        const float* p2 = xl + (size_t)s2 * F + cbase;
        const float* p3 = xl + (size_t)s3 * F + cbase;
        if constexpr (V == 4) {
            float4 t0 = *(const float4*)p0;
            float4 t1 = *(const float4*)p1;
            float4 t2 = *(const float4*)p2;
            float4 t3 = *(const float4*)p3;
            a[0][0]=t0.x; a[0][1]=t0.y; a[0][2]=t0.z; a[0][3]=t0.w;
            a[1][0]=t1.x; a[1][1]=t1.y; a[1][2]=t1.z; a[1][3]=t1.w;
            a[2][0]=t2.x; a[2][1]=t2.y; a[2][2]=t2.z; a[2][3]=t2.w;
            a[3][0]=t3.x; a[3][1]=t3.y; a[3][2]=t3.z; a[3][3]=t3.w;
        } else {
            float2 t0 = *(const float2*)p0;
            float2 t1 = *(const float2*)p1;
            float2 t2 = *(const float2*)p2;
            float2 t3 = *(const float2*)p3;
            a[0][0]=t0.x; a[0][1]=t0.y;
            a[1][0]=t1.x; a[1][1]=t1.y;
            a[2][0]=t2.x; a[2][1]=t2.y;
            a[3][0]=t3.x; a[3][1]=t3.y;
        }
        float part[4];
#pragma unroll
        for (int e4 = 0; e4 < 4; e4++) {
            float pp = 0.f;
#pragma unroll
            for (int j = 0; j < V; j++) {
                float s = a[e4][j] + xrv[j];
                s = (s > 0.f) ? s : 0.2f * s;
                pp += s * attv[j];
            }
            part[e4] = pp;
        }
#pragma unroll
        for (int off = G / 2; off > 0; off >>= 1) {
#pragma unroll
            for (int e4 = 0; e4 < 4; e4++)
                part[e4] += __shfl_xor_sync(0xffffffffu, part[e4], off);
        }
        float p0v = __expf(part[0]);
        float p1v = __expf(part[1]);
        float p2v = __expf(part[2]);
        float p3v = __expf(part[3]);
        z += (p0v + p1v) + (p2v + p3v);
#pragma unroll
        for (int j = 0; j < V; j++)
            acc[j] += p0v * a[0][j] + p1v * a[1][j] + p2v * a[2][j] + p3v * a[3][j];
    }
    for (; k < end; k++) {
        int s0 = __ldg(g_srcs + k);
        float a0[V];
        const float* p0 = xl + (size_t)s0 * F + cbase;
        if constexpr (V == 4) {
            float4 t0 = *(const float4*)p0;
            a0[0] = t0.x; a0[1] = t0.y; a0[2] = t0.z; a0[3] = t0.w;
        } else {
            float2 t0 = *(const float2*)p0;
            a0[0] = t0.x; a0[1] = t0.y;
        }
        float pp = 0.f;
#pragma unroll
        for (int j = 0; j < V; j++) {
            float s = a0[j] + xrv[j];
            s = (s > 0.f) ? s : 0.2f * s;
            pp += s * attv[j];
        }
#pragma unroll
        for (int off = G / 2; off > 0; off >>= 1)
            pp += __shfl_xor_sync(0xffffffffu, pp, off);
        float pv = __expf(pp);
        z += pv;
#pragma unroll
        for (int j = 0; j < V; j++) acc[j] += pv * a0[j];
    }

    float inv = 1.f / (z + 1e-16f);
    float ov[V];
#pragma unroll
    for (int j = 0; j < V; j++) {
        float v = acc[j] * inv + bias[cbase + j];
        if constexpr (ELU) v = (v > 0.f) ? v : (__expf(v) - 1.f);
        ov[j] = v;
    }
    float* op = out + (size_t)i * F + cbase;
    if constexpr (V == 4)
        *(float4*)op = make_float4(ov[0], ov[1], ov[2], ov[3]);
    else
        *(float2*)op = make_float2(ov[0], ov[1]);
}

// ---------------- launch ----------------

extern "C" void kernel_launch(void* const* d_in, const int* in_sizes, int n_in,
                              void* d_out, int out_size) {
    const float* x    = (const float*)d_in[0];
    const int*   ei   = (const int*)d_in[1];
    const float* Wl1  = (const float*)d_in[2];
    const float* bl1  = (const float*)d_in[3];
    const float* Wr1  = (const float*)d_in[4];
    const float* br1  = (const float*)d_in[5];
    const float* att1 = (const float*)d_in[6];
    const float* bias1= (const float*)d_in[7];
    const float* Wl2  = (const float*)d_in[8];
    const float* bl2  = (const float*)d_in[9];
    const float* Wr2  = (const float*)d_in[10];
    const float* br2  = (const float*)d_in[11];
    const float* att2 = (const float*)d_in[12];
    const float* bias2= (const float*)d_in[13];
    float* out = (float*)d_out;

    int n = in_sizes[0] / 64;   // 50000
    int e = in_sizes[1] / 2;    // 850000
    const int* src = ei;
    const int* dst = ei + e;
    // int4 paths require 16B alignment of src/dst; fall back to e4=0 otherwise
    int e4 = 0;
    if ((((unsigned long long)(size_t)src) & 15ull) == 0 &&
        (((unsigned long long)(size_t)dst) & 15ull) == 0) e4 = e / 4;

    float *xlp, *xrp, *hp, *wtp;
    int* degp;
    cudaGetSymbolAddress((void**)&xlp, g_xl);
    cudaGetSymbolAddress((void**)&xrp, g_xr);
    cudaGetSymbolAddress((void**)&hp,  g_h);
    cudaGetSymbolAddress((void**)&wtp, g_wt);
    cudaGetSymbolAddress((void**)&degp, g_deg);

    // one-time stream/event creation (first call is the uncaptured
    // correctness run; capture sees only record/wait nodes)
    static cudaStream_t s_side = nullptr;
    static cudaEvent_t ev_fork = nullptr, ev_join = nullptr;
    if (s_side == nullptr) {
        cudaStreamCreateWithFlags(&s_side, cudaStreamNonBlocking);
        cudaEventCreateWithFlags(&ev_fork, cudaEventDisableTiming);
        cudaEventCreateWithFlags(&ev_join, cudaEventDisableTiming);
    }

    // fork: CSR build on side stream, concurrent with wt + linear1 on main
    cudaEventRecord(ev_fork, 0);
    cudaStreamWaitEvent(s_side, ev_fork, 0);

    cudaMemsetAsync(degp, 0, n * sizeof(int), s_side);
    count_kernel<<<(max(e4, 1) + 255) / 256, 256, 0, s_side>>>(
        (const int4*)dst, e4, dst, e);
    scan_kernel<<<1, 1024, 0, s_side>>>(n);
    scatter_kernel<<<(max(e4, 1) + 255) / 256, 256, 0, s_side>>>(
        (const int4*)src, (const int4*)dst, e4, src, dst, e);
    cudaEventRecord(ev_join, s_side);

    // main stream: weight transpose + layer-1 linears
    wt_kernel<<<128, 256>>>(Wl1, Wr1, Wl2, Wr2);
    dim3 lgrid((n + 63) / 64, 2);
    linear2_kernel<64, 128><<<lgrid, 256>>>(
        x, wtp, bl1, xlp, wtp + 8192, br1, xrp, n);

    // join: gat1 needs CSR + linear1
    cudaStreamWaitEvent(0, ev_join, 0);

    gat_kernel<4, 32, true><<<(n + 7) / 8, 256>>>(xlp, xrp, att1, bias1, hp, n);

    linear2_kernel<128, 64><<<lgrid, 256>>>(
        hp, wtp + 16384, bl2, xlp, wtp + 24576, br2, xrp, n);
    gat_kernel<1, 64, false><<<(n + 7) / 8, 256>>>(xlp, xrp, att2, bias2, out, n);
}

// round 7
// speedup vs baseline: 1.5231x; 1.1016x over previous
#include <cuda_runtime.h>
#include <math.h>
#include <stdint.h>

#define NN 50000
#define EE 850000

// -------- device scratch (no allocations allowed) --------
__device__ int g_deg[NN];
__device__ int g_cursor[NN];
__device__ int g_rowptr[NN + 1];
__device__ int g_srcs[EE];
__device__ float g_xl[(size_t)NN * 128];
__device__ float g_xr[(size_t)NN * 128];
__device__ float g_h[(size_t)NN * 128];
__device__ float g_wt[4 * 8192];   // transposed weights

// ---------------- f32x2 packed math helpers ----------------
__device__ __forceinline__ unsigned long long pack2(float x) {
    unsigned long long r;
    asm("mov.b64 %0, {%1, %1};" : "=l"(r) : "f"(x));
    return r;
}
__device__ __forceinline__ unsigned long long fma2(unsigned long long a,
                                                   unsigned long long b,
                                                   unsigned long long c) {
    unsigned long long d;
    asm("fma.rn.f32x2 %0, %1, %2, %3;" : "=l"(d) : "l"(a), "l"(b), "l"(c));
    return d;
}
__device__ __forceinline__ float2 unpack2(unsigned long long v) {
    float2 r;
    asm("mov.b64 {%0, %1}, %2;" : "=f"(r.x), "=f"(r.y) : "l"(v));
    return r;
}

// ---------------- CSR build ----------------

__global__ void count_kernel(const int4* __restrict__ dst4, int e4,
                             const int* __restrict__ dst, int e) {
    int i = blockIdx.x * blockDim.x + threadIdx.x;
    if (i < e4) {
        int4 d = dst4[i];
        atomicAdd(&g_deg[d.x], 1);
        atomicAdd(&g_deg[d.y], 1);
        atomicAdd(&g_deg[d.z], 1);
        atomicAdd(&g_deg[d.w], 1);
    }
    if (i == 0) {
        for (int k = 4 * e4; k < e; k++) atomicAdd(&g_deg[dst[k]], 1);
    }
}

// single-block exclusive scan; chunk=52 keeps every thread's range 4-aligned
// so loads and rowptr/cursor writes vectorize as int4.
__global__ void scan_kernel(int n) {
    __shared__ int sdata[1024];
    int t = threadIdx.x;
    const int ch = 52;                       // 52*1024 >= 50000, 52%4==0
    int s0 = t * ch;
    int s1 = min(s0 + ch, n);
    int sum = 0;
    if (s0 < n) {
        int i = s0;
        for (; i + 4 <= s1; i += 4) {
            int4 d = *(const int4*)(g_deg + i);
            sum += d.x + d.y + d.z + d.w;
        }
        for (; i < s1; i++) sum += g_deg[i];
    }
    sdata[t] = sum;
    __syncthreads();
    for (int off = 1; off < 1024; off <<= 1) {
        int v = (t >= off) ? sdata[t - off] : 0;
        __syncthreads();
        sdata[t] += v;
        __syncthreads();
    }
    int run = sdata[t] - sum;
    if (s0 < n) {
        int i = s0;
        for (; i + 4 <= s1; i += 4) {
            int4 d = *(const int4*)(g_deg + i);
            int4 r;
            r.x = run;
            r.y = r.x + d.x;
            r.z = r.y + d.y;
            r.w = r.z + d.z;
            run = r.w + d.w;
            *(int4*)(g_rowptr + i) = r;
            *(int4*)(g_cursor + i) = r;
        }
        for (; i < s1; i++) {
            g_rowptr[i] = run;
            g_cursor[i] = run;
            run += g_deg[i];
        }
    }
    if (t == 1023) g_rowptr[n] = run;
}

__global__ void scatter_kernel(const int4* __restrict__ src4,
                               const int4* __restrict__ dst4, int e4,
                               const int* __restrict__ src,
                               const int* __restrict__ dst, int e) {
    int i = blockIdx.x * blockDim.x + threadIdx.x;
    if (i < e4) {
        int4 s = src4[i];
        int4 d = dst4[i];
        g_srcs[atomicAdd(&g_cursor[d.x], 1)] = s.x;
        g_srcs[atomicAdd(&g_cursor[d.y], 1)] = s.y;
        g_srcs[atomicAdd(&g_cursor[d.z], 1)] = s.z;
        g_srcs[atomicAdd(&g_cursor[d.w], 1)] = s.w;
    }
    if (i == 0) {
        for (int k = 4 * e4; k < e; k++)
            g_srcs[atomicAdd(&g_cursor[dst[k]], 1)] = src[k];
    }
}

// ---------------- weight transpose (tiny, once per launch) ----------------
__global__ void wt_kernel(const float* __restrict__ Wl1,
                          const float* __restrict__ Wr1,
                          const float* __restrict__ Wl2,
                          const float* __restrict__ Wr2) {
    int idx = blockIdx.x * blockDim.x + threadIdx.x;   // 0 .. 32767
    int m = idx >> 13;
    int r = idx & 8191;
    const float* W = (m == 0) ? Wl1 : (m == 1) ? Wr1 : (m == 2) ? Wl2 : Wr2;
    int fin = (m < 2) ? 64 : 128;
    int fout = (m < 2) ? 128 : 64;
    int k = r / fout;
    int o = r - k * fout;
    g_wt[idx] = W[o * fin + k];   // Wt[k][o] = W[o][k]
}

// ---------------- smem dual linear: y = x @ W^T + b ----------------
template <int FIN, int FOUT>
__global__ void __launch_bounds__(256)
linear2_kernel(const float* __restrict__ x,
               const float* __restrict__ Wt0,
               const float* __restrict__ b0,
               float* __restrict__ y0,
               const float* __restrict__ Wt1,
               const float* __restrict__ b1,
               float* __restrict__ y1,
               int n) {
    constexpr int BN = 64;
    constexpr int KC = 32;
    constexpr int OT = FOUT / 4;     // 32 or 16
    constexpr int NT = 256 / OT;     // 8 or 16
    constexpr int NPT = BN / NT;     // 8 or 4
    constexpr int NP = NPT / 2;      // node pairs per thread: 4 or 2

    __shared__ float sW[KC * FOUT];
    __shared__ float sX[KC * BN];

    const float* Wt = blockIdx.y ? Wt1 : Wt0;
    const float* b = blockIdx.y ? b1 : b0;
    float* y = blockIdx.y ? y1 : y0;

    int tid = threadIdx.x;
    int ot = tid % OT;
    int nt = tid / OT;
    int nbase = blockIdx.x * BN;
    int n0 = nt * NPT;

    unsigned long long acc[NP][4];
#pragma unroll
    for (int q = 0; q < NP; q++)
#pragma unroll
        for (int j = 0; j < 4; j++) acc[q][j] = 0ull;

    for (int kc = 0; kc < FIN; kc += KC) {
        __syncthreads();
        {
            const float4* wsrc = (const float4*)(Wt + (size_t)kc * FOUT);
#pragma unroll
            for (int idx = tid; idx < KC * FOUT / 4; idx += 256)
                ((float4*)sW)[idx] = wsrc[idx];
        }
#pragma unroll
        for (int idx = tid; idx < (KC / 4) * BN; idx += 256) {
            int nn = idx % BN;
            int c4 = idx / BN;
            int node = nbase + nn;
            float4 xv = make_float4(0.f, 0.f, 0.f, 0.f);
            if (node < n) xv = *(const float4*)(x + (size_t)node * FIN + kc + 4 * c4);
            sX[(4 * c4 + 0) * BN + nn] = xv.x;
            sX[(4 * c4 + 1) * BN + nn] = xv.y;
            sX[(4 * c4 + 2) * BN + nn] = xv.z;
            sX[(4 * c4 + 3) * BN + nn] = xv.w;
        }
        __syncthreads();

#pragma unroll 8
        for (int k = 0; k < KC; k++) {
            float4 w = *(const float4*)(sW + k * FOUT + 4 * ot);
            unsigned long long w0 = pack2(w.x);
            unsigned long long w1 = pack2(w.y);
            unsigned long long w2 = pack2(w.z);
            unsigned long long w3 = pack2(w.w);
            const ulonglong2* xp = (const ulonglong2*)(sX + k * BN + n0);
#pragma unroll
            for (int q2 = 0; q2 < NP / 2; q2++) {
                ulonglong2 xv = xp[q2];
                acc[2 * q2][0] = fma2(xv.x, w0, acc[2 * q2][0]);
                acc[2 * q2][1] = fma2(xv.x, w1, acc[2 * q2][1]);
                acc[2 * q2][2] = fma2(xv.x, w2, acc[2 * q2][2]);
                acc[2 * q2][3] = fma2(xv.x, w3, acc[2 * q2][3]);
                acc[2 * q2 + 1][0] = fma2(xv.y, w0, acc[2 * q2 + 1][0]);
                acc[2 * q2 + 1][1] = fma2(xv.y, w1, acc[2 * q2 + 1][1]);
                acc[2 * q2 + 1][2] = fma2(xv.y, w2, acc[2 * q2 + 1][2]);
                acc[2 * q2 + 1][3] = fma2(xv.y, w3, acc[2 * q2 + 1][3]);
            }
        }
    }

    float4 bv = *(const float4*)(b + 4 * ot);
#pragma unroll
    for (int q = 0; q < NP; q++) {
        float2 o0 = unpack2(acc[q][0]);
        float2 o1 = unpack2(acc[q][1]);
        float2 o2 = unpack2(acc[q][2]);
        float2 o3 = unpack2(acc[q][3]);
        int na = nbase + n0 + 2 * q;
        if (na < n)
            *(float4*)(y + (size_t)na * FOUT + 4 * ot) =
                make_float4(o0.x + bv.x, o1.x + bv.y, o2.x + bv.z, o3.x + bv.w);
        if (na + 1 < n)
            *(float4*)(y + (size_t)(na + 1) * FOUT + 4 * ot) =
                make_float4(o0.y + bv.x, o1.y + bv.y, o2.y + bv.z, o3.y + bv.w);
    }
}

// ---------------- fused GATv2 edge phase ----------------
// U-edge pipelined block: U gathers issued back-to-back, then compute.
template <int U, int V, int G>
__device__ __forceinline__ void gat_block(const float* __restrict__ xl,
                                          const int* sidx, int cbase,
                                          const float (&xrv)[V],
                                          const float (&attv)[V],
                                          float (&acc)[V], float& z) {
    float a[U][V];
#pragma unroll
    for (int u = 0; u < U; u++) {
        const float* p = xl + (size_t)sidx[u] * (32 * V) + cbase;
        if constexpr (V == 4) {
            float4 t = *(const float4*)p;
            a[u][0] = t.x; a[u][1] = t.y; a[u][2] = t.z; a[u][3] = t.w;
        } else {
            float2 t = *(const float2*)p;
            a[u][0] = t.x; a[u][1] = t.y;
        }
    }
    float part[U];
#pragma unroll
    for (int u = 0; u < U; u++) {
        float pp = 0.f;
#pragma unroll
        for (int j = 0; j < V; j++) {
            float s = a[u][j] + xrv[j];
            s = (s > 0.f) ? s : 0.2f * s;
            pp += s * attv[j];
        }
        part[u] = pp;
    }
#pragma unroll
    for (int off = G / 2; off > 0; off >>= 1) {
#pragma unroll
        for (int u = 0; u < U; u++)
            part[u] += __shfl_xor_sync(0xffffffffu, part[u], off);
    }
    float p[U];
#pragma unroll
    for (int u = 0; u < U; u++) p[u] = __expf(part[u]);
#pragma unroll
    for (int u = 0; u < U; u++) z += p[u];
#pragma unroll
    for (int j = 0; j < V; j++) {
        float s = 0.f;
#pragma unroll
        for (int u = 0; u < U; u++) s += p[u] * a[u][j];
        acc[j] += s;
    }
}

template <int H, int C, bool ELU>
__global__ void gat_kernel(const float* __restrict__ xl,
                           const float* __restrict__ xr,
                           const float* __restrict__ att,
                           const float* __restrict__ bias,
                           float* __restrict__ out, int n) {
    constexpr int F = H * C;
    constexpr int V = F / 32;
    constexpr int G = 32 / H;

    int wid = (blockIdx.x * blockDim.x + threadIdx.x) >> 5;
    int lane = threadIdx.x & 31;
    if (wid >= n) return;
    int i = wid;
    int cbase = lane * V;

    float xrv[V], attv[V], acc[V];
    {
        const float* xp = xr + (size_t)i * F + cbase;
        if constexpr (V == 4) {
            float4 t = *(const float4*)xp;
            xrv[0] = t.x; xrv[1] = t.y; xrv[2] = t.z; xrv[3] = t.w;
        } else {
            float2 t = *(const float2*)xp;
            xrv[0] = t.x; xrv[1] = t.y;
        }
    }
#pragma unroll
    for (int j = 0; j < V; j++) { attv[j] = att[cbase + j]; acc[j] = 0.f; }

    float z = 0.f;
    int beg = g_rowptr[i], end = g_rowptr[i + 1];
    int k = beg;

    for (; k + 8 <= end; k += 8) {
        int s[8];
#pragma unroll
        for (int u = 0; u < 8; u++) s[u] = __ldg(g_srcs + k + u);
        gat_block<8, V, G>(xl, s, cbase, xrv, attv, acc, z);
    }
    if (k + 4 <= end) {
        int s[4];
#pragma unroll
        for (int u = 0; u < 4; u++) s[u] = __ldg(g_srcs + k + u);
        gat_block<4, V, G>(xl, s, cbase, xrv, attv, acc, z);
        k += 4;
    }
    for (; k < end; k++) {
        int s[1] = {__ldg(g_srcs + k)};
        gat_block<1, V, G>(xl, s, cbase, xrv, attv, acc, z);
    }

    float inv = 1.f / (z + 1e-16f);
    float ov[V];
#pragma unroll
    for (int j = 0; j < V; j++) {
        float v = acc[j] * inv + bias[cbase + j];
        if constexpr (ELU) v = (v > 0.f) ? v : (__expf(v) - 1.f);
        ov[j] = v;
    }
    float* op = out + (size_t)i * F + cbase;
    if constexpr (V == 4)
        *(float4*)op = make_float4(ov[0], ov[1], ov[2], ov[3]);
    else
        *(float2*)op = make_float2(ov[0], ov[1]);
}

// ---------------- launch ----------------

extern "C" void kernel_launch(void* const* d_in, const int* in_sizes, int n_in,
                              void* d_out, int out_size) {
    const float* x    = (const float*)d_in[0];
    const int*   ei   = (const int*)d_in[1];
    const float* Wl1  = (const float*)d_in[2];
    const float* bl1  = (const float*)d_in[3];
    const float* Wr1  = (const float*)d_in[4];
    const float* br1  = (const float*)d_in[5];
    const float* att1 = (const float*)d_in[6];
    const float* bias1= (const float*)d_in[7];
    const float* Wl2  = (const float*)d_in[8];
    const float* bl2  = (const float*)d_in[9];
    const float* Wr2  = (const float*)d_in[10];
    const float* br2  = (const float*)d_in[11];
    const float* att2 = (const float*)d_in[12];
    const float* bias2= (const float*)d_in[13];
    float* out = (float*)d_out;

    int n = in_sizes[0] / 64;   // 50000
    int e = in_sizes[1] / 2;    // 850000
    const int* src = ei;
    const int* dst = ei + e;
    int e4 = 0;
    if ((((unsigned long long)(size_t)src) & 15ull) == 0 &&
        (((unsigned long long)(size_t)dst) & 15ull) == 0) e4 = e / 4;

    float *xlp, *xrp, *hp, *wtp;
    int* degp;
    cudaGetSymbolAddress((void**)&xlp, g_xl);
    cudaGetSymbolAddress((void**)&xrp, g_xr);
    cudaGetSymbolAddress((void**)&hp,  g_h);
    cudaGetSymbolAddress((void**)&wtp, g_wt);
    cudaGetSymbolAddress((void**)&degp, g_deg);

    static cudaStream_t s_side = nullptr;
    static cudaEvent_t ev_fork = nullptr, ev_join = nullptr;
    if (s_side == nullptr) {
        cudaStreamCreateWithFlags(&s_side, cudaStreamNonBlocking);
        cudaEventCreateWithFlags(&ev_fork, cudaEventDisableTiming);
        cudaEventCreateWithFlags(&ev_join, cudaEventDisableTiming);
    }

    // fork: CSR build on side stream, concurrent with wt + linear1 on main
    cudaEventRecord(ev_fork, 0);
    cudaStreamWaitEvent(s_side, ev_fork, 0);

    cudaMemsetAsync(degp, 0, n * sizeof(int), s_side);
    count_kernel<<<(max(e4, 1) + 255) / 256, 256, 0, s_side>>>(
        (const int4*)dst, e4, dst, e);
    scan_kernel<<<1, 1024, 0, s_side>>>(n);
    scatter_kernel<<<(max(e4, 1) + 255) / 256, 256, 0, s_side>>>(
        (const int4*)src, (const int4*)dst, e4, src, dst, e);
    cudaEventRecord(ev_join, s_side);

    // main stream: weight transpose + layer-1 linears
    wt_kernel<<<128, 256>>>(Wl1, Wr1, Wl2, Wr2);
    dim3 lgrid((n + 63) / 64, 2);
    linear2_kernel<64, 128><<<lgrid, 256>>>(
        x, wtp, bl1, xlp, wtp + 8192, br1, xrp, n);

    // join: gat1 needs CSR + linear1
    cudaStreamWaitEvent(0, ev_join, 0);

    gat_kernel<4, 32, true><<<(n + 7) / 8, 256>>>(xlp, xrp, att1, bias1, hp, n);

    linear2_kernel<128, 64><<<lgrid, 256>>>(
        hp, wtp + 16384, bl2, xlp, wtp + 24576, br2, xrp, n);
    gat_kernel<1, 64, false><<<(n + 7) / 8, 256>>>(xlp, xrp, att2, bias2, out, n);
}

// round 8
// speedup vs baseline: 1.5847x; 1.0405x over previous
#include <cuda_runtime.h>
#include <cuda_fp16.h>
#include <math.h>
#include <stdint.h>

#define NN 50000
#define EE 850000

// -------- device scratch (no allocations allowed) --------
__device__ int g_deg[NN];
__device__ int g_cursor[NN];
__device__ int g_rowptr[NN + 1];
__device__ int g_srcs[EE];
__device__ __half g_xlh[(size_t)NN * 128];  // fp16 xl operand (both layers)
__device__ float g_xr[(size_t)NN * 128];    // fp32 xr operand (both layers)
__device__ float g_h[(size_t)NN * 128];     // layer-1 output (fp32)
__device__ float g_wt[4 * 8192];            // transposed weights

// ---------------- f32x2 packed math helpers ----------------
__device__ __forceinline__ unsigned long long pack2(float x) {
    unsigned long long r;
    asm("mov.b64 %0, {%1, %1};" : "=l"(r) : "f"(x));
    return r;
}
__device__ __forceinline__ unsigned long long fma2(unsigned long long a,
                                                   unsigned long long b,
                                                   unsigned long long c) {
    unsigned long long d;
    asm("fma.rn.f32x2 %0, %1, %2, %3;" : "=l"(d) : "l"(a), "l"(b), "l"(c));
    return d;
}
__device__ __forceinline__ float2 unpack2(unsigned long long v) {
    float2 r;
    asm("mov.b64 {%0, %1}, %2;" : "=f"(r.x), "=f"(r.y) : "l"(v));
    return r;
}

// ---------------- CSR build ----------------

__global__ void count_kernel(const int4* __restrict__ dst4, int e4,
                             const int* __restrict__ dst, int e) {
    int i = blockIdx.x * blockDim.x + threadIdx.x;
    if (i < e4) {
        int4 d = dst4[i];
        atomicAdd(&g_deg[d.x], 1);
        atomicAdd(&g_deg[d.y], 1);
        atomicAdd(&g_deg[d.z], 1);
        atomicAdd(&g_deg[d.w], 1);
    }
    if (i == 0) {
        for (int k = 4 * e4; k < e; k++) atomicAdd(&g_deg[dst[k]], 1);
    }
}

// single-block exclusive scan; chunk=52 keeps ranges 4-aligned (int4 I/O)
__global__ void scan_kernel(int n) {
    __shared__ int sdata[1024];
    int t = threadIdx.x;
    const int ch = 52;
    int s0 = t * ch;
    int s1 = min(s0 + ch, n);
    int sum = 0;
    if (s0 < n) {
        int i = s0;
        for (; i + 4 <= s1; i += 4) {
            int4 d = *(const int4*)(g_deg + i);
            sum += d.x + d.y + d.z + d.w;
        }
        for (; i < s1; i++) sum += g_deg[i];
    }
    sdata[t] = sum;
    __syncthreads();
    for (int off = 1; off < 1024; off <<= 1) {
        int v = (t >= off) ? sdata[t - off] : 0;
        __syncthreads();
        sdata[t] += v;
        __syncthreads();
    }
    int run = sdata[t] - sum;
    if (s0 < n) {
        int i = s0;
        for (; i + 4 <= s1; i += 4) {
            int4 d = *(const int4*)(g_deg + i);
            int4 r;
            r.x = run;
            r.y = r.x + d.x;
            r.z = r.y + d.y;
            r.w = r.z + d.z;
            run = r.w + d.w;
            *(int4*)(g_rowptr + i) = r;
            *(int4*)(g_cursor + i) = r;
        }
        for (; i < s1; i++) {
            g_rowptr[i] = run;
            g_cursor[i] = run;
            run += g_deg[i];
        }
    }
    if (t == 1023) g_rowptr[n] = run;
}

__global__ void scatter_kernel(const int4* __restrict__ src4,
                               const int4* __restrict__ dst4, int e4,
                               const int* __restrict__ src,
                               const int* __restrict__ dst, int e) {
    int i = blockIdx.x * blockDim.x + threadIdx.x;
    if (i < e4) {
        int4 s = src4[i];
        int4 d = dst4[i];
        g_srcs[atomicAdd(&g_cursor[d.x], 1)] = s.x;
        g_srcs[atomicAdd(&g_cursor[d.y], 1)] = s.y;
        g_srcs[atomicAdd(&g_cursor[d.z], 1)] = s.z;
        g_srcs[atomicAdd(&g_cursor[d.w], 1)] = s.w;
    }
    if (i == 0) {
        for (int k = 4 * e4; k < e; k++)
            g_srcs[atomicAdd(&g_cursor[dst[k]], 1)] = src[k];
    }
}

// ---------------- weight transpose (tiny, hidden under side chain) ----------
__global__ void wt_kernel(const float* __restrict__ Wl1,
                          const float* __restrict__ Wr1,
                          const float* __restrict__ Wl2,
                          const float* __restrict__ Wr2) {
    int idx = blockIdx.x * blockDim.x + threadIdx.x;   // 0 .. 32767
    int m = idx >> 13;
    int r = idx & 8191;
    const float* W = (m == 0) ? Wl1 : (m == 1) ? Wr1 : (m == 2) ? Wl2 : Wr2;
    int fin = (m < 2) ? 64 : 128;
    int fout = (m < 2) ? 128 : 64;
    int k = r / fout;
    int o = r - k * fout;
    g_wt[idx] = W[o * fin + k];   // Wt[k][o] = W[o][k]
}

// ---------------- smem dual linear ----------------
// branch 0 (blockIdx.y==0): y = x@Wl^T+bl, stored as fp16 (xl operand)
// branch 1 (blockIdx.y==1): y = x@Wr^T+br, stored as fp32 (xr operand)
template <int FIN, int FOUT>
__global__ void __launch_bounds__(256)
linear2_kernel(const float* __restrict__ x,
               const float* __restrict__ Wt0,
               const float* __restrict__ b0,
               __half* __restrict__ y0h,
               const float* __restrict__ Wt1,
               const float* __restrict__ b1,
               float* __restrict__ y1f,
               int n) {
    constexpr int BN = 64;
    constexpr int KC = 32;
    constexpr int OT = FOUT / 4;     // 32 or 16
    constexpr int NT = 256 / OT;     // 8 or 16
    constexpr int NPT = BN / NT;     // 8 or 4
    constexpr int NP = NPT / 2;      // node pairs per thread

    __shared__ float sW[KC * FOUT];
    __shared__ float sX[KC * BN];

    const float* Wt = blockIdx.y ? Wt1 : Wt0;
    const float* b = blockIdx.y ? b1 : b0;

    int tid = threadIdx.x;
    int ot = tid % OT;
    int nt = tid / OT;
    int nbase = blockIdx.x * BN;
    int n0 = nt * NPT;

    unsigned long long acc[NP][4];
#pragma unroll
    for (int q = 0; q < NP; q++)
#pragma unroll
        for (int j = 0; j < 4; j++) acc[q][j] = 0ull;

    for (int kc = 0; kc < FIN; kc += KC) {
        __syncthreads();
        {
            const float4* wsrc = (const float4*)(Wt + (size_t)kc * FOUT);
#pragma unroll
            for (int idx = tid; idx < KC * FOUT / 4; idx += 256)
                ((float4*)sW)[idx] = wsrc[idx];
        }
#pragma unroll
        for (int idx = tid; idx < (KC / 4) * BN; idx += 256) {
            int nn = idx % BN;
            int c4 = idx / BN;
            int node = nbase + nn;
            float4 xv = make_float4(0.f, 0.f, 0.f, 0.f);
            if (node < n) xv = *(const float4*)(x + (size_t)node * FIN + kc + 4 * c4);
            sX[(4 * c4 + 0) * BN + nn] = xv.x;
            sX[(4 * c4 + 1) * BN + nn] = xv.y;
            sX[(4 * c4 + 2) * BN + nn] = xv.z;
            sX[(4 * c4 + 3) * BN + nn] = xv.w;
        }
        __syncthreads();

#pragma unroll 8
        for (int k = 0; k < KC; k++) {
            float4 w = *(const float4*)(sW + k * FOUT + 4 * ot);
            unsigned long long w0 = pack2(w.x);
            unsigned long long w1 = pack2(w.y);
            unsigned long long w2 = pack2(w.z);
            unsigned long long w3 = pack2(w.w);
            const ulonglong2* xp = (const ulonglong2*)(sX + k * BN + n0);
#pragma unroll
            for (int q2 = 0; q2 < NP / 2; q2++) {
                ulonglong2 xv = xp[q2];
                acc[2 * q2][0] = fma2(xv.x, w0, acc[2 * q2][0]);
                acc[2 * q2][1] = fma2(xv.x, w1, acc[2 * q2][1]);
                acc[2 * q2][2] = fma2(xv.x, w2, acc[2 * q2][2]);
                acc[2 * q2][3] = fma2(xv.x, w3, acc[2 * q2][3]);
                acc[2 * q2 + 1][0] = fma2(xv.y, w0, acc[2 * q2 + 1][0]);
                acc[2 * q2 + 1][1] = fma2(xv.y, w1, acc[2 * q2 + 1][1]);
                acc[2 * q2 + 1][2] = fma2(xv.y, w2, acc[2 * q2 + 1][2]);
                acc[2 * q2 + 1][3] = fma2(xv.y, w3, acc[2 * q2 + 1][3]);
            }
        }
    }

    float4 bv = *(const float4*)(b + 4 * ot);
#pragma unroll
    for (int q = 0; q < NP; q++) {
        float2 o0 = unpack2(acc[q][0]);
        float2 o1 = unpack2(acc[q][1]);
        float2 o2 = unpack2(acc[q][2]);
        float2 o3 = unpack2(acc[q][3]);
        int na = nbase + n0 + 2 * q;
        float4 va = make_float4(o0.x + bv.x, o1.x + bv.y, o2.x + bv.z, o3.x + bv.w);
        float4 vb = make_float4(o0.y + bv.x, o1.y + bv.y, o2.y + bv.z, o3.y + bv.w);
        if (blockIdx.y == 0) {
            if (na < n) {
                __half2* yp = (__half2*)(y0h + (size_t)na * FOUT + 4 * ot);
                yp[0] = __floats2half2_rn(va.x, va.y);
                yp[1] = __floats2half2_rn(va.z, va.w);
            }
            if (na + 1 < n) {
                __half2* yp = (__half2*)(y0h + (size_t)(na + 1) * FOUT + 4 * ot);
                yp[0] = __floats2half2_rn(vb.x, vb.y);
                yp[1] = __floats2half2_rn(vb.z, vb.w);
            }
        } else {
            if (na < n)
                *(float4*)(y1f + (size_t)na * FOUT + 4 * ot) = va;
            if (na + 1 < n)
                *(float4*)(y1f + (size_t)(na + 1) * FOUT + 4 * ot) = vb;
        }
    }
}

// ---------------- fused GATv2 edge phase (fp16 gathers) ----------------
template <int U, int V, int G>
__device__ __forceinline__ void gat_block(const __half* __restrict__ xlh,
                                          const int* sidx, int cbase,
                                          const float (&xrv)[V],
                                          const float (&attv)[V],
                                          float (&acc)[V], float& z) {
    float a[U][V];
#pragma unroll
    for (int u = 0; u < U; u++) {
        const __half* p = xlh + (size_t)sidx[u] * (32 * V) + cbase;
        if constexpr (V == 4) {
            uint2 raw = *(const uint2*)p;
            float2 f0 = __half22float2(*reinterpret_cast<__half2*>(&raw.x));
            float2 f1 = __half22float2(*reinterpret_cast<__half2*>(&raw.y));
            a[u][0] = f0.x; a[u][1] = f0.y; a[u][2] = f1.x; a[u][3] = f1.y;
        } else {
            unsigned raw = *(const unsigned*)p;
            float2 f0 = __half22float2(*reinterpret_cast<__half2*>(&raw));
            a[u][0] = f0.x; a[u][1] = f0.y;
        }
    }
    float part[U];
#pragma unroll
    for (int u = 0; u < U; u++) {
        float pp = 0.f;
#pragma unroll
        for (int j = 0; j < V; j++) {
            float s = a[u][j] + xrv[j];
            s = (s > 0.f) ? s : 0.2f * s;
            pp += s * attv[j];
        }
        part[u] = pp;
    }
#pragma unroll
    for (int off = G / 2; off > 0; off >>= 1) {
#pragma unroll
        for (int u = 0; u < U; u++)
            part[u] += __shfl_xor_sync(0xffffffffu, part[u], off);
    }
    float p[U];
#pragma unroll
    for (int u = 0; u < U; u++) p[u] = __expf(part[u]);
#pragma unroll
    for (int u = 0; u < U; u++) z += p[u];
#pragma unroll
    for (int j = 0; j < V; j++) {
        float s = 0.f;
#pragma unroll
        for (int u = 0; u < U; u++) s += p[u] * a[u][j];
        acc[j] += s;
    }
}

template <int H, int C, bool ELU>
__global__ void gat_kernel(const __half* __restrict__ xlh,
                           const float* __restrict__ xr,
                           const float* __restrict__ att,
                           const float* __restrict__ bias,
                           float* __restrict__ out, int n) {
    constexpr int F = H * C;
    constexpr int V = F / 32;
    constexpr int G = 32 / H;

    int wid = (blockIdx.x * blockDim.x + threadIdx.x) >> 5;
    int lane = threadIdx.x & 31;
    if (wid >= n) return;
    int i = wid;
    int cbase = lane * V;

    float xrv[V], attv[V], acc[V];
    {
        const float* xp = xr + (size_t)i * F + cbase;
        if constexpr (V == 4) {
            float4 t = *(const float4*)xp;
            xrv[0] = t.x; xrv[1] = t.y; xrv[2] = t.z; xrv[3] = t.w;
        } else {
            float2 t = *(const float2*)xp;
            xrv[0] = t.x; xrv[1] = t.y;
        }
    }
#pragma unroll
    for (int j = 0; j < V; j++) { attv[j] = att[cbase + j]; acc[j] = 0.f; }

    float z = 0.f;
    int beg = g_rowptr[i], end = g_rowptr[i + 1];
    int k = beg;

    for (; k + 8 <= end; k += 8) {
        int s[8];
#pragma unroll
        for (int u = 0; u < 8; u++) s[u] = __ldg(g_srcs + k + u);
        gat_block<8, V, G>(xlh, s, cbase, xrv, attv, acc, z);
    }
    if (k + 4 <= end) {
        int s[4];
#pragma unroll
        for (int u = 0; u < 4; u++) s[u] = __ldg(g_srcs + k + u);
        gat_block<4, V, G>(xlh, s, cbase, xrv, attv, acc, z);
        k += 4;
    }
    for (; k < end; k++) {
        int s[1] = {__ldg(g_srcs + k)};
        gat_block<1, V, G>(xlh, s, cbase, xrv, attv, acc, z);
    }

    float inv = 1.f / (z + 1e-16f);
    float ov[V];
#pragma unroll
    for (int j = 0; j < V; j++) {
        float v = acc[j] * inv + bias[cbase + j];
        if constexpr (ELU) v = (v > 0.f) ? v : (__expf(v) - 1.f);
        ov[j] = v;
    }
    float* op = out + (size_t)i * F + cbase;
    if constexpr (V == 4)
        *(float4*)op = make_float4(ov[0], ov[1], ov[2], ov[3]);
    else
        *(float2*)op = make_float2(ov[0], ov[1]);
}

// ---------------- launch ----------------

extern "C" void kernel_launch(void* const* d_in, const int* in_sizes, int n_in,
                              void* d_out, int out_size) {
    const float* x    = (const float*)d_in[0];
    const int*   ei   = (const int*)d_in[1];
    const float* Wl1  = (const float*)d_in[2];
    const float* bl1  = (const float*)d_in[3];
    const float* Wr1  = (const float*)d_in[4];
    const float* br1  = (const float*)d_in[5];
    const float* att1 = (const float*)d_in[6];
    const float* bias1= (const float*)d_in[7];
    const float* Wl2  = (const float*)d_in[8];
    const float* bl2  = (const float*)d_in[9];
    const float* Wr2  = (const float*)d_in[10];
    const float* br2  = (const float*)d_in[11];
    const float* att2 = (const float*)d_in[12];
    const float* bias2= (const float*)d_in[13];
    float* out = (float*)d_out;

    int n = in_sizes[0] / 64;   // 50000
    int e = in_sizes[1] / 2;    // 850000
    const int* src = ei;
    const int* dst = ei + e;
    int e4 = 0;
    if ((((unsigned long long)(size_t)src) & 15ull) == 0 &&
        (((unsigned long long)(size_t)dst) & 15ull) == 0) e4 = e / 4;

    __half* xlhp;
    float *xrp, *hp, *wtp;
    int* degp;
    cudaGetSymbolAddress((void**)&xlhp, g_xlh);
    cudaGetSymbolAddress((void**)&xrp, g_xr);
    cudaGetSymbolAddress((void**)&hp,  g_h);
    cudaGetSymbolAddress((void**)&wtp, g_wt);
    cudaGetSymbolAddress((void**)&degp, g_deg);

    static cudaStream_t s_side = nullptr;
    static cudaEvent_t ev_fork = nullptr, ev_join = nullptr;
    if (s_side == nullptr) {
        cudaStreamCreateWithFlags(&s_side, cudaStreamNonBlocking);
        cudaEventCreateWithFlags(&ev_fork, cudaEventDisableTiming);
        cudaEventCreateWithFlags(&ev_join, cudaEventDisableTiming);
    }

    // fork: CSR build on side stream, concurrent with wt + linear1 on main
    cudaEventRecord(ev_fork, 0);
    cudaStreamWaitEvent(s_side, ev_fork, 0);

    cudaMemsetAsync(degp, 0, n * sizeof(int), s_side);
    count_kernel<<<(max(e4, 1) + 255) / 256, 256, 0, s_side>>>(
        (const int4*)dst, e4, dst, e);
    scan_kernel<<<1, 1024, 0, s_side>>>(n);
    scatter_kernel<<<(max(e4, 1) + 255) / 256, 256, 0, s_side>>>(
        (const int4*)src, (const int4*)dst, e4, src, dst, e);
    cudaEventRecord(ev_join, s_side);

    // main stream: weight transpose + layer-1 linears
    wt_kernel<<<128, 256>>>(Wl1, Wr1, Wl2, Wr2);
    dim3 lgrid((n + 63) / 64, 2);
    linear2_kernel<64, 128><<<lgrid, 256>>>(
        x, wtp, bl1, xlhp, wtp + 8192, br1, xrp, n);

    // join: gat1 needs CSR + linear1
    cudaStreamWaitEvent(0, ev_join, 0);

    gat_kernel<4, 32, true><<<(n + 7) / 8, 256>>>(xlhp, xrp, att1, bias1, hp, n);

    linear2_kernel<128, 64><<<lgrid, 256>>>(
        hp, wtp + 16384, bl2, xlhp, wtp + 24576, br2, xrp, n);
    gat_kernel<1, 64, false><<<(n + 7) / 8, 256>>>(xlhp, xrp, att2, bias2, out, n);
}